// round 1
// baseline (speedup 1.0000x reference)
#include <cuda_runtime.h>

#define BATCH 1024
#define FDIM 39
#define DDIM 64
#define ODIM 128

// Scratch for inter-layer activations (no cudaMalloc allowed).
__device__ float g_X1[BATCH * ODIM * DDIM];
__device__ float g_X2[BATCH * ODIM * DDIM];

#define FMA_X2(d_, a_, b_, c_) \
    asm("fma.rn.f32x2 %0, %1, %2, %3;" : "=l"(d_) : "l"(a_), "l"(b_), "l"(c_))
#define PACK2(d_, x_, y_) \
    asm("mov.b64 %0, {%1, %2};" : "=l"(d_) : "r"(x_), "r"(y_))
#define UNPACK2(x_, y_, d_) \
    asm("mov.b64 {%0, %1}, %2;" : "=r"(x_), "=r"(y_) : "l"(d_))

// One CTA per sample. Computes X_next = W @ P + bias, where
// P[c,d] = X0[h,d] * Xi[m,d], c = h*M + m, generated on the fly in smem.
// Also writes the sum-pool over d into out[b, out_off : out_off+128].
template <int M>
__global__ __launch_bounds__(128, 3) void cin_layer(
    const float* __restrict__ X0, const float* __restrict__ Xi,
    const float* __restrict__ W, const float* __restrict__ bias,
    float* __restrict__ Xout, float* __restrict__ out, int out_off)
{
    constexpr int C  = FDIM * M;          // 1521 or 4992
    constexpr int KT = 32;                // K tile
    constexpr int NT = (C + KT - 1) / KT; // number of K tiles

    __shared__ float x0s[FDIM * DDIM];    // 39 x 64
    __shared__ float Wt[ODIM * 33];       // [o][k], padded row 33 (conflict-free)
    __shared__ float Pt[KT * DDIM];       // [k][d]

    const int b   = blockIdx.x;
    const int tid = threadIdx.x;
    const int dx  = tid & 7;   // d-group: covers d in {4dx..4dx+3, 32+4dx..32+4dx+3}
    const int oy  = tid >> 3;  // o-group: covers o in {8oy..8oy+7}

    // Stage X0 slice for this sample (coalesced).
    for (int f = tid; f < FDIM * DDIM; f += 128)
        x0s[f] = X0[b * FDIM * DDIM + f];

    unsigned long long acc[8][4];
#pragma unroll
    for (int j = 0; j < 8; ++j)
#pragma unroll
        for (int p = 0; p < 4; ++p) acc[j][p] = 0ull;

    const float* __restrict__ Xib = Xi + b * M * DDIM;

    for (int t = 0; t < NT; ++t) {
        const int c0 = t * KT;
        __syncthreads();  // first pass: guards x0s; later: guards prev compute

        // ---- Stage W tile: Wt[o][k] = W[o][c0+k], zeros past C ----
#pragma unroll
        for (int i = 0; i < 8; ++i) {
            const int f  = i * 128 + tid;
            const int o  = f >> 3;
            const int kq = f & 7;
            const int c  = c0 + kq * 4;
            float w0 = 0.f, w1 = 0.f, w2 = 0.f, w3 = 0.f;
            if constexpr (C % 4 == 0) {
                // layers 2/3: C=4992 -> rows 16B aligned, full tiles
                const float4 v = *reinterpret_cast<const float4*>(W + o * C + c);
                w0 = v.x; w1 = v.y; w2 = v.z; w3 = v.w;
            } else {
                // layer 1: C=1521, scalar guarded loads
                if (c + 0 < C) w0 = W[o * C + c + 0];
                if (c + 1 < C) w1 = W[o * C + c + 1];
                if (c + 2 < C) w2 = W[o * C + c + 2];
                if (c + 3 < C) w3 = W[o * C + c + 3];
            }
            float* wrow = &Wt[o * 33 + kq * 4];
            wrow[0] = w0; wrow[1] = w1; wrow[2] = w2; wrow[3] = w3;
        }

        // ---- Stage P tile: Pt[k][d] = x0s[h][d] * Xi[m][d], c = c0+k ----
#pragma unroll
        for (int i = 0; i < 16; ++i) {
            const int f = i * 128 + tid;
            const int k = f >> 6;
            const int d = f & 63;
            const int c = c0 + k;
            float v = 0.f;
            if (C % KT == 0 || c < C) {
                const int h = c / M;
                const int m = c - h * M;
                v = x0s[h * DDIM + d] * __ldg(&Xib[m * DDIM + d]);
            }
            Pt[k * DDIM + d] = v;
        }
        __syncthreads();

        // ---- Compute: 8o x 8d register tile, packed f32x2 FMAs ----
#pragma unroll 4
        for (int k = 0; k < KT; ++k) {
            const uint4 bv0 = *reinterpret_cast<const uint4*>(&Pt[k * DDIM + dx * 4]);
            const uint4 bv1 = *reinterpret_cast<const uint4*>(&Pt[k * DDIM + 32 + dx * 4]);
            unsigned long long bf[4];
            PACK2(bf[0], bv0.x, bv0.y);
            PACK2(bf[1], bv0.z, bv0.w);
            PACK2(bf[2], bv1.x, bv1.y);
            PACK2(bf[3], bv1.z, bv1.w);
#pragma unroll
            for (int j = 0; j < 8; ++j) {
                const float w = Wt[(oy * 8 + j) * 33 + k];
                const unsigned int wu = __float_as_uint(w);
                unsigned long long wp;
                PACK2(wp, wu, wu);
#pragma unroll
                for (int p = 0; p < 4; ++p)
                    FMA_X2(acc[j][p], wp, bf[p], acc[j][p]);
            }
        }
    }

    // ---- Epilogue: bias, store X_next, sum-pool via width-8 shfl ----
#pragma unroll
    for (int j = 0; j < 8; ++j) {
        const int o = oy * 8 + j;
        const float bo = bias[o];
        float e[8];
#pragma unroll
        for (int p = 0; p < 4; ++p) {
            unsigned int lo, hi;
            UNPACK2(lo, hi, acc[j][p]);
            e[p * 2]     = __uint_as_float(lo) + bo;
            e[p * 2 + 1] = __uint_as_float(hi) + bo;
        }
        if (Xout) {
            float4 v0 = {e[0], e[1], e[2], e[3]};
            float4 v1 = {e[4], e[5], e[6], e[7]};
            *reinterpret_cast<float4*>(&Xout[b * ODIM * DDIM + o * DDIM + dx * 4]) = v0;
            *reinterpret_cast<float4*>(&Xout[b * ODIM * DDIM + o * DDIM + 32 + dx * 4]) = v1;
        }
        float s = e[0] + e[1] + e[2] + e[3] + e[4] + e[5] + e[6] + e[7];
        s += __shfl_down_sync(0xffffffffu, s, 4, 8);
        s += __shfl_down_sync(0xffffffffu, s, 2, 8);
        s += __shfl_down_sync(0xffffffffu, s, 1, 8);
        if (dx == 0) out[b * 384 + out_off + o] = s;
    }
}

extern "C" void kernel_launch(void* const* d_in, const int* in_sizes, int n_in,
                              void* d_out, int out_size)
{
    const float* X0 = (const float*)d_in[0];
    const float* W1 = (const float*)d_in[1];
    const float* b1 = (const float*)d_in[2];
    const float* W2 = (const float*)d_in[3];
    const float* b2 = (const float*)d_in[4];
    const float* W3 = (const float*)d_in[5];
    const float* b3 = (const float*)d_in[6];
    float* out = (float*)d_out;

    float *X1p = nullptr, *X2p = nullptr;
    cudaGetSymbolAddress((void**)&X1p, g_X1);
    cudaGetSymbolAddress((void**)&X2p, g_X2);

    cin_layer<39><<<BATCH, 128>>>(X0, X0, W1, b1, X1p, out, 0);
    cin_layer<128><<<BATCH, 128>>>(X0, X1p, W2, b2, X2p, out, 128);
    cin_layer<128><<<BATCH, 128>>>(X0, X2p, W3, b3, nullptr, out, 256);
}

// round 4
// speedup vs baseline: 1.9763x; 1.9763x over previous
#include <cuda_runtime.h>
#include <cuda_bf16.h>
#include <cstdint>

#define BATCH 1024
#define FDIM 39
#define DDIM 64
#define ODIM 128
#define G 2          // samples per CTA
#define KT 32        // K tile

// ---------------- scratch (no cudaMalloc allowed) ----------------
__device__ float g_X1[BATCH * ODIM * DDIM];
__device__ float g_X2[BATCH * ODIM * DDIM];
__device__ alignas(16) __nv_bfloat16 g_W1hi[ODIM * 1536], g_W1lo[ODIM * 1536];
__device__ alignas(16) __nv_bfloat16 g_W2hi[ODIM * 4992], g_W2lo[ODIM * 4992];
__device__ alignas(16) __nv_bfloat16 g_W3hi[ODIM * 4992], g_W3lo[ODIM * 4992];

// ---------------- smem layout ----------------
// x0s: G*39*64 f32 = 19968 B
// stage (x2): Ahi 128x80B | Alo | Bhi 32x272B | Blo
#define A_STRIDE 80
#define B_STRIDE 272
#define OFF_AHI 0
#define OFF_ALO 10240
#define OFF_BHI 20480
#define OFF_BLO 29184
#define STG_SZ  37888
#define OFF_STG 19968
#define SMEM_TOT (OFF_STG + 2 * STG_SZ)   // 95744

__device__ __forceinline__ uint32_t smem_u32(const void* p) {
    uint32_t a;
    asm("{ .reg .u64 t; cvta.to.shared.u64 t, %1; cvt.u32.u64 %0, t; }" : "=r"(a) : "l"(p));
    return a;
}

#define LDSM_X4(r, addr) \
    asm volatile("ldmatrix.sync.aligned.m8n8.x4.shared.b16 {%0,%1,%2,%3}, [%4];" \
        : "=r"((r)[0]), "=r"((r)[1]), "=r"((r)[2]), "=r"((r)[3]) : "r"(addr))
#define LDSM_X4T(r, addr) \
    asm volatile("ldmatrix.sync.aligned.m8n8.x4.trans.shared.b16 {%0,%1,%2,%3}, [%4];" \
        : "=r"((r)[0]), "=r"((r)[1]), "=r"((r)[2]), "=r"((r)[3]) : "r"(addr))

__device__ __forceinline__ void mma16816(float* c, const uint32_t* a, const uint32_t* b) {
    asm volatile("mma.sync.aligned.m16n8k16.row.col.f32.bf16.bf16.f32 "
        "{%0,%1,%2,%3}, {%4,%5,%6,%7}, {%8,%9}, {%0,%1,%2,%3};"
        : "+f"(c[0]), "+f"(c[1]), "+f"(c[2]), "+f"(c[3])
        : "r"(a[0]), "r"(a[1]), "r"(a[2]), "r"(a[3]), "r"(b[0]), "r"(b[1]));
}

// ---------------- W pre-split (fp32 -> bf16 hi/lo, zero padded) ----------------
__global__ void split_w_kernel(const float* __restrict__ W, __nv_bfloat16* __restrict__ hi,
                               __nv_bfloat16* __restrict__ lo, int C, int Cpad) {
    int i = blockIdx.x * 256 + threadIdx.x;
    if (i >= ODIM * Cpad) return;
    int o = i / Cpad, cp = i - o * Cpad;
    float w = (cp < C) ? W[o * C + cp] : 0.f;
    __nv_bfloat16 h = __float2bfloat16(w);
    hi[i] = h;
    lo[i] = __float2bfloat16(w - __bfloat162float(h));
}

// ---------------- main CIN layer: warp-level bf16 HMMA, 3-split ----------------
template <int M_, int C_, int CPAD_>
__global__ __launch_bounds__(256, 2) void cin_hmma(
    const float* __restrict__ X0, const float* __restrict__ Xi,
    const __nv_bfloat16* __restrict__ Whi, const __nv_bfloat16* __restrict__ Wlo,
    const float* __restrict__ bias, float* __restrict__ Xout,
    float* __restrict__ out, int out_off)
{
    extern __shared__ char smem[];
    constexpr int NT = CPAD_ / KT;

    const int tid = threadIdx.x, wid = tid >> 5, lane = tid & 31;
    const int b0 = blockIdx.x * G;
    const int warp_m = wid >> 1;       // 0..3 -> o block of 32
    const int warp_n = wid & 1;        // sample g

    float* x0s = (float*)smem;

    // W staging map: 2 threads per o-row, 32B each
    const int wrow = tid >> 1, whalf = tid & 1;
    // B gen map: 2 consecutive n per thread, 8 k's
    const int n2 = (tid & 63) * 2;                 // 0..126 even
    const int gg = n2 >> 6, dd = n2 & 63;
    const int kh = tid >> 6;                       // 0..3 -> k group of 8

    const float* Xi_g = Xi + (size_t)(b0 + gg) * M_ * DDIM;
    const float* x0_g = x0s + gg * FDIM * DDIM;

    // stage X0 (both samples, coalesced)
    for (int i = tid; i < G * FDIM * DDIM; i += 256)
        x0s[i] = X0[(size_t)b0 * FDIM * DDIM + i];

    float acc[2][8][4];
#pragma unroll
    for (int a = 0; a < 2; ++a)
#pragma unroll
        for (int b = 0; b < 8; ++b)
#pragma unroll
            for (int c = 0; c < 4; ++c) acc[a][b][c] = 0.f;

    auto load_tile = [&](int t) {
        char* sb = smem + OFF_STG + (t & 1) * STG_SZ;
        const int c0 = t * KT;
        // ---- stage W hi/lo tiles: rows padded to 80B ----
        {
            const uint4* sh = (const uint4*)(Whi + (size_t)wrow * CPAD_ + c0) + whalf * 2;
            const uint4* sl = (const uint4*)(Wlo + (size_t)wrow * CPAD_ + c0) + whalf * 2;
            uint4 h0 = sh[0], h1 = sh[1];
            uint4 l0 = sl[0], l1 = sl[1];
            char* dh = sb + OFF_AHI + wrow * A_STRIDE + whalf * 32;
            char* dl = sb + OFF_ALO + wrow * A_STRIDE + whalf * 32;
            *(uint4*)(dh) = h0; *(uint4*)(dh + 16) = h1;
            *(uint4*)(dl) = l0; *(uint4*)(dl + 16) = l1;
        }
        // ---- generate B tiles: B[k][n] = x0[h][d]*Xi[m][d], hi/lo split ----
#pragma unroll
        for (int j = 0; j < 8; ++j) {
            const int k = kh * 8 + j;
            const int c = c0 + k;
            float p0 = 0.f, p1 = 0.f;
            if ((CPAD_ == C_) || c < C_) {
                int h, m;
                if (M_ == 128) { h = c >> 7; m = c & 127; }
                else           { h = c / M_; m = c - h * M_; }
                const float2 xv = *(const float2*)(x0_g + h * DDIM + dd);
                const float2 iv = __ldg((const float2*)(Xi_g + m * DDIM + dd));
                p0 = xv.x * iv.x;
                p1 = xv.y * iv.y;
            }
            __nv_bfloat16 h0 = __float2bfloat16(p0), h1 = __float2bfloat16(p1);
            float r0 = p0 - __bfloat162float(h0), r1 = p1 - __bfloat162float(h1);
            __nv_bfloat16 l0 = __float2bfloat16(r0), l1 = __float2bfloat16(r1);
            uint32_t hp = ((uint32_t)__bfloat16_as_ushort(h1) << 16) | __bfloat16_as_ushort(h0);
            uint32_t lp = ((uint32_t)__bfloat16_as_ushort(l1) << 16) | __bfloat16_as_ushort(l0);
            *(uint32_t*)(sb + OFF_BHI + k * B_STRIDE + n2 * 2) = hp;
            *(uint32_t*)(sb + OFF_BLO + k * B_STRIDE + n2 * 2) = lp;
        }
    };

    __syncthreads();      // x0s ready (needed by load_tile's B gen)
    load_tile(0);
    __syncthreads();

    const uint32_t stg_u32 = smem_u32(smem + OFF_STG);
    const int lr = lane & 15, lc = lane >> 4;

    for (int t = 0; t < NT; ++t) {
        if (t + 1 < NT) load_tile(t + 1);   // prefetch into other buffer

        const uint32_t sb = stg_u32 + (t & 1) * STG_SZ;
        const uint32_t a_hi = sb + OFF_AHI, a_lo = sb + OFF_ALO;
        const uint32_t b_hi = sb + OFF_BHI, b_lo = sb + OFF_BLO;

#pragma unroll
        for (int kb = 0; kb < 2; ++kb) {
            // A fragments: rows warp_m*32 + mf*16, k block kb*16
            uint32_t ah[2][4], al[2][4];
#pragma unroll
            for (int mf = 0; mf < 2; ++mf) {
                const uint32_t row = warp_m * 32 + mf * 16 + lr;
                const uint32_t aoff = row * A_STRIDE + kb * 32 + lc * 16;
                LDSM_X4(ah[mf], a_hi + aoff);
                LDSM_X4(al[mf], a_lo + aoff);
            }
            // B fragments in groups of 2 n8-tiles; n offset includes sample
#pragma unroll
            for (int i = 0; i < 4; ++i) {
                uint32_t bh[4], bl[4];
                const uint32_t boff = (kb * 16 + lr) * B_STRIDE +
                                      (warp_n * 64 + i * 16) * 2 + lc * 16;
                LDSM_X4T(bh, b_hi + boff);
                LDSM_X4T(bl, b_lo + boff);
#pragma unroll
                for (int mf = 0; mf < 2; ++mf) {
                    mma16816(acc[mf][2 * i],     ah[mf], bh);
                    mma16816(acc[mf][2 * i],     ah[mf], bl);
                    mma16816(acc[mf][2 * i],     al[mf], bh);
                    mma16816(acc[mf][2 * i + 1], ah[mf], bh + 2);
                    mma16816(acc[mf][2 * i + 1], ah[mf], bl + 2);
                    mma16816(acc[mf][2 * i + 1], al[mf], bh + 2);
                }
            }
        }
        __syncthreads();
    }

    // ---- epilogue: bias, Xout store, sum-pool ----
    const int g = warp_n;
#pragma unroll
    for (int mf = 0; mf < 2; ++mf) {
        const int r0 = warp_m * 32 + mf * 16 + (lane >> 2);
        const int r1 = r0 + 8;
        const float bv0 = bias[r0], bv1 = bias[r1];
        float s0 = 0.f, s1 = 0.f;
#pragma unroll
        for (int nf = 0; nf < 8; ++nf) {
            float* c = acc[mf][nf];
            s0 += c[0] + c[1];
            s1 += c[2] + c[3];
            if (Xout) {
                const int d = nf * 8 + (lane & 3) * 2;
                float2 v0 = { c[0] + bv0, c[1] + bv0 };
                float2 v1 = { c[2] + bv1, c[3] + bv1 };
                *(float2*)(Xout + (size_t)(b0 + g) * ODIM * DDIM + r0 * DDIM + d) = v0;
                *(float2*)(Xout + (size_t)(b0 + g) * ODIM * DDIM + r1 * DDIM + d) = v1;
            }
        }
        s0 += __shfl_xor_sync(0xffffffffu, s0, 1);
        s0 += __shfl_xor_sync(0xffffffffu, s0, 2);
        s1 += __shfl_xor_sync(0xffffffffu, s1, 1);
        s1 += __shfl_xor_sync(0xffffffffu, s1, 2);
        if ((lane & 3) == 0) {
            out[(size_t)(b0 + g) * 384 + out_off + r0] = s0 + 64.f * bv0;
            out[(size_t)(b0 + g) * 384 + out_off + r1] = s1 + 64.f * bv1;
        }
    }
}

// ---------------- launch ----------------
extern "C" void kernel_launch(void* const* d_in, const int* in_sizes, int n_in,
                              void* d_out, int out_size)
{
    const float* X0 = (const float*)d_in[0];
    const float* W1 = (const float*)d_in[1];
    const float* b1 = (const float*)d_in[2];
    const float* W2 = (const float*)d_in[3];
    const float* b2 = (const float*)d_in[4];
    const float* W3 = (const float*)d_in[5];
    const float* b3 = (const float*)d_in[6];
    float* out = (float*)d_out;

    float *X1p, *X2p;
    __nv_bfloat16 *W1h, *W1l, *W2h, *W2l, *W3h, *W3l;
    cudaGetSymbolAddress((void**)&X1p, g_X1);
    cudaGetSymbolAddress((void**)&X2p, g_X2);
    cudaGetSymbolAddress((void**)&W1h, g_W1hi);
    cudaGetSymbolAddress((void**)&W1l, g_W1lo);
    cudaGetSymbolAddress((void**)&W2h, g_W2hi);
    cudaGetSymbolAddress((void**)&W2l, g_W2lo);
    cudaGetSymbolAddress((void**)&W3h, g_W3hi);
    cudaGetSymbolAddress((void**)&W3l, g_W3lo);

    cudaFuncSetAttribute(cin_hmma<39, 1521, 1536>,  cudaFuncAttributeMaxDynamicSharedMemorySize, SMEM_TOT);
    cudaFuncSetAttribute(cin_hmma<128, 4992, 4992>, cudaFuncAttributeMaxDynamicSharedMemorySize, SMEM_TOT);

    split_w_kernel<<<(ODIM * 1536 + 255) / 256, 256>>>(W1, W1h, W1l, 1521, 1536);
    split_w_kernel<<<(ODIM * 4992 + 255) / 256, 256>>>(W2, W2h, W2l, 4992, 4992);
    split_w_kernel<<<(ODIM * 4992 + 255) / 256, 256>>>(W3, W3h, W3l, 4992, 4992);

    cin_hmma<39, 1521, 1536><<<BATCH / G, 256, SMEM_TOT>>>(X0, X0, W1h, W1l, b1, X1p, out, 0);
    cin_hmma<128, 4992, 4992><<<BATCH / G, 256, SMEM_TOT>>>(X0, X1p, W2h, W2l, b2, X2p, out, 128);
    cin_hmma<128, 4992, 4992><<<BATCH / G, 256, SMEM_TOT>>>(X0, X2p, W3h, W3l, b3, nullptr, out, 256);
}

// round 5
// speedup vs baseline: 2.3873x; 1.2079x over previous
#include <cuda_runtime.h>
#include <cuda_bf16.h>
#include <cstdint>

#define BATCH 1024
#define FDIM 39
#define DDIM 64
#define ODIM 128
#define G 2
#define KT 32

// ---------------- scratch ----------------
__device__ float g_X1[BATCH * ODIM * DDIM];
__device__ float g_X2[BATCH * ODIM * DDIM];
__device__ alignas(16) __nv_bfloat16 g_W1hi[ODIM * 1536], g_W1lo[ODIM * 1536];
__device__ alignas(16) __nv_bfloat16 g_W2hi[ODIM * 4992], g_W2lo[ODIM * 4992];
__device__ alignas(16) __nv_bfloat16 g_W3hi[ODIM * 4992], g_W3lo[ODIM * 4992];

// ---------------- smem layout ----------------
// x0s:  G*39*64 f32          = 19968
// xis:  G*32*64 f32 (L2/3)   = 16384
// 2 stages: Ahi 128x80 | Alo | Bhi 32x272 | Blo  (37888 each)
#define A_STRIDE 80
#define B_STRIDE 272
#define OFF_AHI 0
#define OFF_ALO 10240
#define OFF_BHI 20480
#define OFF_BLO 29184
#define STG_SZ  37888
#define OFF_XIS 19968
#define OFF_STG 36352
#define SMEM_TOT (OFF_STG + 2 * STG_SZ)   // 112128

__device__ __forceinline__ uint32_t smem_u32(const void* p) {
    uint32_t a;
    asm("{ .reg .u64 t; cvta.to.shared.u64 t, %1; cvt.u32.u64 %0, t; }" : "=r"(a) : "l"(p));
    return a;
}

#define CP_ASYNC16(dst, src) \
    asm volatile("cp.async.cg.shared.global [%0], [%1], 16;" :: "r"(dst), "l"(src))
#define CP_COMMIT() asm volatile("cp.async.commit_group;")
#define CP_WAIT0()  asm volatile("cp.async.wait_group 0;")

#define LDSM_X4(r, addr) \
    asm volatile("ldmatrix.sync.aligned.m8n8.x4.shared.b16 {%0,%1,%2,%3}, [%4];" \
        : "=r"((r)[0]), "=r"((r)[1]), "=r"((r)[2]), "=r"((r)[3]) : "r"(addr))
#define LDSM_X4T(r, addr) \
    asm volatile("ldmatrix.sync.aligned.m8n8.x4.trans.shared.b16 {%0,%1,%2,%3}, [%4];" \
        : "=r"((r)[0]), "=r"((r)[1]), "=r"((r)[2]), "=r"((r)[3]) : "r"(addr))

__device__ __forceinline__ void mma16816(float* c, const uint32_t* a, const uint32_t* b) {
    asm volatile("mma.sync.aligned.m16n8k16.row.col.f32.bf16.bf16.f32 "
        "{%0,%1,%2,%3}, {%4,%5,%6,%7}, {%8,%9}, {%0,%1,%2,%3};"
        : "+f"(c[0]), "+f"(c[1]), "+f"(c[2]), "+f"(c[3])
        : "r"(a[0]), "r"(a[1]), "r"(a[2]), "r"(a[3]), "r"(b[0]), "r"(b[1]));
}

// split product into bf16 hi/lo and store to B tiles
__device__ __forceinline__ void split_store(char* bhi, char* blo, int k, int n2,
                                            float p0, float p1) {
    __nv_bfloat16 h0 = __float2bfloat16(p0), h1 = __float2bfloat16(p1);
    float r0 = p0 - __bfloat162float(h0), r1 = p1 - __bfloat162float(h1);
    __nv_bfloat16 l0 = __float2bfloat16(r0), l1 = __float2bfloat16(r1);
    uint32_t hp = ((uint32_t)__bfloat16_as_ushort(h1) << 16) | __bfloat16_as_ushort(h0);
    uint32_t lp = ((uint32_t)__bfloat16_as_ushort(l1) << 16) | __bfloat16_as_ushort(l0);
    *(uint32_t*)(bhi + k * B_STRIDE + n2 * 2) = hp;
    *(uint32_t*)(blo + k * B_STRIDE + n2 * 2) = lp;
}

// stage W hi/lo tiles via cp.async (rows padded to 80B)
template <int CPAD_>
__device__ __forceinline__ void stage_w(uint32_t sb, const __nv_bfloat16* Whi,
                                        const __nv_bfloat16* Wlo, int c0,
                                        int wrow, int whalf) {
    const char* sh = (const char*)(Whi + (size_t)wrow * CPAD_ + c0) + whalf * 32;
    const char* sl = (const char*)(Wlo + (size_t)wrow * CPAD_ + c0) + whalf * 32;
    uint32_t dh = sb + OFF_AHI + wrow * A_STRIDE + whalf * 32;
    uint32_t dl = sb + OFF_ALO + wrow * A_STRIDE + whalf * 32;
    CP_ASYNC16(dh, sh);       CP_ASYNC16(dh + 16, sh + 16);
    CP_ASYNC16(dl, sl);       CP_ASYNC16(dl + 16, sl + 16);
    CP_COMMIT();
}

// MMA over one staged tile: batched frags, term-ordered (distance-8 chains)
__device__ __forceinline__ void mma_tile(uint32_t sb, int warp_m, int warp_n,
                                         int lr, int lc, float acc[2][8][4]) {
#pragma unroll
    for (int kb = 0; kb < 2; ++kb) {
        uint32_t ah[2][4], al[2][4];
#pragma unroll
        for (int mf = 0; mf < 2; ++mf) {
            const uint32_t aoff = (warp_m * 32 + mf * 16 + lr) * A_STRIDE + kb * 32 + lc * 16;
            LDSM_X4(ah[mf], sb + OFF_AHI + aoff);
            LDSM_X4(al[mf], sb + OFF_ALO + aoff);
        }
#pragma unroll
        for (int ip = 0; ip < 2; ++ip) {
            uint32_t bh[2][4], bl[2][4];
#pragma unroll
            for (int ii = 0; ii < 2; ++ii) {
                const int i = ip * 2 + ii;
                const uint32_t boff = (kb * 16 + lr) * B_STRIDE +
                                      (warp_n * 64 + i * 16) * 2 + lc * 16;
                LDSM_X4T(bh[ii], sb + OFF_BHI + boff);
                LDSM_X4T(bl[ii], sb + OFF_BLO + boff);
            }
            // term hh (8 independent), then hl, then lh
#pragma unroll
            for (int mf = 0; mf < 2; ++mf)
#pragma unroll
                for (int ii = 0; ii < 2; ++ii) {
                    mma16816(acc[mf][(ip * 2 + ii) * 2],     ah[mf], bh[ii]);
                    mma16816(acc[mf][(ip * 2 + ii) * 2 + 1], ah[mf], bh[ii] + 2);
                }
#pragma unroll
            for (int mf = 0; mf < 2; ++mf)
#pragma unroll
                for (int ii = 0; ii < 2; ++ii) {
                    mma16816(acc[mf][(ip * 2 + ii) * 2],     ah[mf], bl[ii]);
                    mma16816(acc[mf][(ip * 2 + ii) * 2 + 1], ah[mf], bl[ii] + 2);
                }
#pragma unroll
            for (int mf = 0; mf < 2; ++mf)
#pragma unroll
                for (int ii = 0; ii < 2; ++ii) {
                    mma16816(acc[mf][(ip * 2 + ii) * 2],     al[mf], bh[ii]);
                    mma16816(acc[mf][(ip * 2 + ii) * 2 + 1], al[mf], bh[ii] + 2);
                }
        }
    }
}

__device__ __forceinline__ void epilogue(float acc[2][8][4], const float* bias,
                                         float* Xout, float* out, int out_off,
                                         int b0, int warp_m, int warp_n, int lane) {
    const int g = warp_n;
#pragma unroll
    for (int mf = 0; mf < 2; ++mf) {
        const int r0 = warp_m * 32 + mf * 16 + (lane >> 2);
        const int r1 = r0 + 8;
        const float bv0 = bias[r0], bv1 = bias[r1];
        float s0 = 0.f, s1 = 0.f;
#pragma unroll
        for (int nf = 0; nf < 8; ++nf) {
            float* c = acc[mf][nf];
            s0 += c[0] + c[1];
            s1 += c[2] + c[3];
            if (Xout) {
                const int d = nf * 8 + (lane & 3) * 2;
                float2 v0 = { c[0] + bv0, c[1] + bv0 };
                float2 v1 = { c[2] + bv1, c[3] + bv1 };
                *(float2*)(Xout + (size_t)(b0 + g) * ODIM * DDIM + r0 * DDIM + d) = v0;
                *(float2*)(Xout + (size_t)(b0 + g) * ODIM * DDIM + r1 * DDIM + d) = v1;
            }
        }
        s0 += __shfl_xor_sync(0xffffffffu, s0, 1);
        s0 += __shfl_xor_sync(0xffffffffu, s0, 2);
        s1 += __shfl_xor_sync(0xffffffffu, s1, 1);
        s1 += __shfl_xor_sync(0xffffffffu, s1, 2);
        if ((lane & 3) == 0) {
            out[(size_t)(b0 + g) * 384 + out_off + r0] = s0 + 64.f * bv0;
            out[(size_t)(b0 + g) * 384 + out_off + r1] = s1 + 64.f * bv1;
        }
    }
}

// ---------------- W pre-split ----------------
__global__ void split_w_kernel(const float* __restrict__ W, __nv_bfloat16* __restrict__ hi,
                               __nv_bfloat16* __restrict__ lo, int C, int Cpad) {
    int i = blockIdx.x * 256 + threadIdx.x;
    if (i >= ODIM * Cpad) return;
    int o = i / Cpad, cp = i - o * Cpad;
    float w = (cp < C) ? W[o * C + cp] : 0.f;
    __nv_bfloat16 h = __float2bfloat16(w);
    hi[i] = h;
    lo[i] = __float2bfloat16(w - __bfloat162float(h));
}

// ---------------- Layer 1: Xi == X0, both operands from smem ----------------
__global__ __launch_bounds__(256, 2) void cin_l1(
    const float* __restrict__ X0,
    const __nv_bfloat16* __restrict__ Whi, const __nv_bfloat16* __restrict__ Wlo,
    const float* __restrict__ bias, float* __restrict__ Xout, float* __restrict__ out)
{
    extern __shared__ char smem[];
    constexpr int CPAD_ = 1536, C_ = 1521, NT = CPAD_ / KT;   // 48 tiles

    const int tid = threadIdx.x, wid = tid >> 5, lane = tid & 31;
    const int b0 = blockIdx.x * G;
    const int warp_m = wid >> 1, warp_n = wid & 1;
    const int lr = lane & 15, lc = lane >> 4;
    const int wrow = tid >> 1, whalf = tid & 1;
    const int n2 = (tid & 63) * 2, kh = tid >> 6;
    const int gg = n2 >> 6, dd = n2 & 63;

    float* x0s = (float*)smem;
    const float* x0_g = x0s + gg * FDIM * DDIM;
    const uint32_t stg = smem_u32(smem + OFF_STG);

    for (int i = tid; i < G * FDIM * DDIM; i += 256)
        x0s[i] = X0[(size_t)b0 * FDIM * DDIM + i];

    float acc[2][8][4];
#pragma unroll
    for (int a = 0; a < 2; ++a)
#pragma unroll
        for (int b = 0; b < 8; ++b)
#pragma unroll
            for (int c = 0; c < 4; ++c) acc[a][b][c] = 0.f;

    auto gen = [&](int t) {
        const uint32_t sb = stg + (t & 1) * STG_SZ;
        char* sbc = smem + OFF_STG + (t & 1) * STG_SZ;
        const int c0 = t * KT;
        stage_w<CPAD_>(sb, Whi, Wlo, c0, wrow, whalf);
#pragma unroll
        for (int j = 0; j < 8; ++j) {
            const int k = kh * 8 + j;
            const int c = c0 + k;
            float p0 = 0.f, p1 = 0.f;
            if (c < C_) {
                const int h = c / FDIM;
                const int m = c - h * FDIM;
                const float2 xv = *(const float2*)(x0_g + h * DDIM + dd);
                const float2 iv = *(const float2*)(x0_g + m * DDIM + dd);
                p0 = xv.x * iv.x; p1 = xv.y * iv.y;
            }
            split_store(sbc + OFF_BHI, sbc + OFF_BLO, k, n2, p0, p1);
        }
    };

    __syncthreads();
    gen(0);
    CP_WAIT0();
    __syncthreads();

    for (int t = 0; t < NT; ++t) {
        if (t + 1 < NT) gen(t + 1);
        mma_tile(stg + (t & 1) * STG_SZ, warp_m, warp_n, lr, lc, acc);
        CP_WAIT0();
        __syncthreads();
    }
    epilogue(acc, bias, Xout, out, 0, b0, warp_m, warp_n, lane);
}

// ---------------- Layers 2/3: mb-outer loop, Xi m-block staged in smem ----------------
__global__ __launch_bounds__(256, 2) void cin_l23(
    const float* __restrict__ X0, const float* __restrict__ Xi,
    const __nv_bfloat16* __restrict__ Whi, const __nv_bfloat16* __restrict__ Wlo,
    const float* __restrict__ bias, float* __restrict__ Xout,
    float* __restrict__ out, int out_off)
{
    extern __shared__ char smem[];
    constexpr int CPAD_ = 4992, M_ = 128;

    const int tid = threadIdx.x, wid = tid >> 5, lane = tid & 31;
    const int b0 = blockIdx.x * G;
    const int warp_m = wid >> 1, warp_n = wid & 1;
    const int lr = lane & 15, lc = lane >> 4;
    const int wrow = tid >> 1, whalf = tid & 1;
    const int n2 = (tid & 63) * 2, kh = tid >> 6;
    const int gg = n2 >> 6, dd = n2 & 63;

    float* x0s = (float*)smem;
    float* xis = (float*)(smem + OFF_XIS);
    const float* x0_g = x0s + gg * FDIM * DDIM;
    const float* xi_g = xis + gg * KT * DDIM;
    const uint32_t stg = smem_u32(smem + OFF_STG);
    const uint32_t xis_u32 = smem_u32(xis);

    for (int i = tid; i < G * FDIM * DDIM; i += 256)
        x0s[i] = X0[(size_t)b0 * FDIM * DDIM + i];

    float acc[2][8][4];
#pragma unroll
    for (int a = 0; a < 2; ++a)
#pragma unroll
        for (int b = 0; b < 8; ++b)
#pragma unroll
            for (int c = 0; c < 4; ++c) acc[a][b][c] = 0.f;

    auto gen = [&](int mb, int h, int buf) {
        const uint32_t sb = stg + buf * STG_SZ;
        char* sbc = smem + OFF_STG + buf * STG_SZ;
        const int c0 = h * M_ + mb * KT;
        stage_w<CPAD_>(sb, Whi, Wlo, c0, wrow, whalf);
        const float2 xv = *(const float2*)(x0_g + h * DDIM + dd);
#pragma unroll
        for (int j = 0; j < 8; ++j) {
            const int k = kh * 8 + j;
            const float2 iv = *(const float2*)(xi_g + k * DDIM + dd);
            split_store(sbc + OFF_BHI, sbc + OFF_BLO, k, n2,
                        xv.x * iv.x, xv.y * iv.y);
        }
    };

    int t = 0;
    for (int mb = 0; mb < 4; ++mb) {
        __syncthreads();   // previous mb's gens done reading xis
        // stage Xi m-block (both samples), cp.async 16B x 4 iters
        {
            const int i = tid;                       // 1024 uint4 total, 256 threads
#pragma unroll
            for (int it = 0; it < 4; ++it) {
                const int idx = it * 256 + i;        // uint4 index
                const int g = idx >> 9, rem = idx & 511;
                const float* src = Xi + (size_t)(b0 + g) * M_ * DDIM + mb * KT * DDIM + rem * 4;
                CP_ASYNC16(xis_u32 + idx * 16, src);
            }
            CP_COMMIT();
            CP_WAIT0();
        }
        __syncthreads();
        gen(mb, 0, t & 1);
        CP_WAIT0();
        __syncthreads();
        for (int h = 0; h < FDIM; ++h, ++t) {
            if (h + 1 < FDIM) gen(mb, h + 1, (t + 1) & 1);
            mma_tile(stg + (t & 1) * STG_SZ, warp_m, warp_n, lr, lc, acc);
            CP_WAIT0();
            __syncthreads();
        }
    }
    epilogue(acc, bias, Xout, out, out_off, b0, warp_m, warp_n, lane);
}

// ---------------- launch ----------------
extern "C" void kernel_launch(void* const* d_in, const int* in_sizes, int n_in,
                              void* d_out, int out_size)
{
    const float* X0 = (const float*)d_in[0];
    const float* W1 = (const float*)d_in[1];
    const float* b1 = (const float*)d_in[2];
    const float* W2 = (const float*)d_in[3];
    const float* b2 = (const float*)d_in[4];
    const float* W3 = (const float*)d_in[5];
    const float* b3 = (const float*)d_in[6];
    float* out = (float*)d_out;

    float *X1p, *X2p;
    __nv_bfloat16 *W1h, *W1l, *W2h, *W2l, *W3h, *W3l;
    cudaGetSymbolAddress((void**)&X1p, g_X1);
    cudaGetSymbolAddress((void**)&X2p, g_X2);
    cudaGetSymbolAddress((void**)&W1h, g_W1hi);
    cudaGetSymbolAddress((void**)&W1l, g_W1lo);
    cudaGetSymbolAddress((void**)&W2h, g_W2hi);
    cudaGetSymbolAddress((void**)&W2l, g_W2lo);
    cudaGetSymbolAddress((void**)&W3h, g_W3hi);
    cudaGetSymbolAddress((void**)&W3l, g_W3lo);

    cudaFuncSetAttribute(cin_l1,  cudaFuncAttributeMaxDynamicSharedMemorySize, SMEM_TOT);
    cudaFuncSetAttribute(cin_l23, cudaFuncAttributeMaxDynamicSharedMemorySize, SMEM_TOT);

    split_w_kernel<<<(ODIM * 1536 + 255) / 256, 256>>>(W1, W1h, W1l, 1521, 1536);
    split_w_kernel<<<(ODIM * 4992 + 255) / 256, 256>>>(W2, W2h, W2l, 4992, 4992);
    split_w_kernel<<<(ODIM * 4992 + 255) / 256, 256>>>(W3, W3h, W3l, 4992, 4992);

    cin_l1 <<<BATCH / G, 256, SMEM_TOT>>>(X0, W1h, W1l, b1, X1p, out);
    cin_l23<<<BATCH / G, 256, SMEM_TOT>>>(X0, X1p, W2h, W2l, b2, X2p, out, 128);
    cin_l23<<<BATCH / G, 256, SMEM_TOT>>>(X0, X2p, W3h, W3l, b3, nullptr, out, 256);
}

// round 6
// speedup vs baseline: 3.7807x; 1.5837x over previous
#include <cuda_runtime.h>
#include <cuda_fp16.h>
#include <cstdint>

#define BATCH 1024
#define FDIM 39
#define DDIM 64
#define ODIM 128
#define G 2
#define KT 32

// ---------------- scratch ----------------
__device__ float g_X1[BATCH * ODIM * DDIM];
__device__ float g_X2[BATCH * ODIM * DDIM];
__device__ alignas(16) __half g_W1hi[ODIM * 1536], g_W1lo[ODIM * 1536];
__device__ alignas(16) __half g_W2hi[ODIM * 4992], g_W2lo[ODIM * 4992];
__device__ alignas(16) __half g_W3hi[ODIM * 4992], g_W3lo[ODIM * 4992];

// ---------------- smem layout ----------------
// x0s:  G*39*64 f32          = 19968
// xis:  G*32*64 f32 (L2/3)   = 16384
// 2 stages: Ahi 128x80 | Alo 128x80 | B 32x272   (29184 each)
#define A_STRIDE 80
#define B_STRIDE 272
#define OFF_AHI 0
#define OFF_ALO 10240
#define OFF_B   20480
#define STG_SZ  29184
#define OFF_XIS 19968
#define OFF_STG 36352
#define SMEM_TOT (OFF_STG + 2 * STG_SZ)   // 94720

__device__ __forceinline__ uint32_t smem_u32(const void* p) {
    uint32_t a;
    asm("{ .reg .u64 t; cvta.to.shared.u64 t, %1; cvt.u32.u64 %0, t; }" : "=r"(a) : "l"(p));
    return a;
}

#define CP_ASYNC16(dst, src) \
    asm volatile("cp.async.cg.shared.global [%0], [%1], 16;" :: "r"(dst), "l"(src))
#define CP_COMMIT() asm volatile("cp.async.commit_group;")
#define CP_WAIT0()  asm volatile("cp.async.wait_group 0;")

#define LDSM_X4(r, addr) \
    asm volatile("ldmatrix.sync.aligned.m8n8.x4.shared.b16 {%0,%1,%2,%3}, [%4];" \
        : "=r"((r)[0]), "=r"((r)[1]), "=r"((r)[2]), "=r"((r)[3]) : "r"(addr))
#define LDSM_X4T(r, addr) \
    asm volatile("ldmatrix.sync.aligned.m8n8.x4.trans.shared.b16 {%0,%1,%2,%3}, [%4];" \
        : "=r"((r)[0]), "=r"((r)[1]), "=r"((r)[2]), "=r"((r)[3]) : "r"(addr))

__device__ __forceinline__ void mma16816(float* c, const uint32_t* a, const uint32_t* b) {
    asm volatile("mma.sync.aligned.m16n8k16.row.col.f32.f16.f16.f32 "
        "{%0,%1,%2,%3}, {%4,%5,%6,%7}, {%8,%9}, {%0,%1,%2,%3};"
        : "+f"(c[0]), "+f"(c[1]), "+f"(c[2]), "+f"(c[3])
        : "r"(a[0]), "r"(a[1]), "r"(a[2]), "r"(a[3]), "r"(b[0]), "r"(b[1]));
}

// stage W hi/lo tiles via cp.async (rows padded to 80B)
template <int CPAD_>
__device__ __forceinline__ void stage_w(uint32_t sb, const __half* Whi,
                                        const __half* Wlo, int c0,
                                        int wrow, int whalf) {
    const char* sh = (const char*)(Whi + (size_t)wrow * CPAD_ + c0) + whalf * 32;
    const char* sl = (const char*)(Wlo + (size_t)wrow * CPAD_ + c0) + whalf * 32;
    uint32_t dh = sb + OFF_AHI + wrow * A_STRIDE + whalf * 32;
    uint32_t dl = sb + OFF_ALO + wrow * A_STRIDE + whalf * 32;
    CP_ASYNC16(dh, sh);       CP_ASYNC16(dh + 16, sh + 16);
    CP_ASYNC16(dl, sl);       CP_ASYNC16(dl + 16, sl + 16);
    CP_COMMIT();
}

// MMA over one staged tile: 2 terms (Whi*B, Wlo*B), distance-8 chains
__device__ __forceinline__ void mma_tile(uint32_t sb, int warp_m, int warp_n,
                                         int lr, int lc, float acc[2][8][4]) {
#pragma unroll
    for (int kb = 0; kb < 2; ++kb) {
        uint32_t ah[2][4], al[2][4];
#pragma unroll
        for (int mf = 0; mf < 2; ++mf) {
            const uint32_t aoff = (warp_m * 32 + mf * 16 + lr) * A_STRIDE + kb * 32 + lc * 16;
            LDSM_X4(ah[mf], sb + OFF_AHI + aoff);
            LDSM_X4(al[mf], sb + OFF_ALO + aoff);
        }
#pragma unroll
        for (int ip = 0; ip < 2; ++ip) {
            uint32_t bb[2][4];
#pragma unroll
            for (int ii = 0; ii < 2; ++ii) {
                const int i = ip * 2 + ii;
                const uint32_t boff = (kb * 16 + lr) * B_STRIDE +
                                      (warp_n * 64 + i * 16) * 2 + lc * 16;
                LDSM_X4T(bb[ii], sb + OFF_B + boff);
            }
            // term hi (8 independent accum chains), then lo
#pragma unroll
            for (int mf = 0; mf < 2; ++mf)
#pragma unroll
                for (int ii = 0; ii < 2; ++ii) {
                    mma16816(acc[mf][(ip * 2 + ii) * 2],     ah[mf], bb[ii]);
                    mma16816(acc[mf][(ip * 2 + ii) * 2 + 1], ah[mf], bb[ii] + 2);
                }
#pragma unroll
            for (int mf = 0; mf < 2; ++mf)
#pragma unroll
                for (int ii = 0; ii < 2; ++ii) {
                    mma16816(acc[mf][(ip * 2 + ii) * 2],     al[mf], bb[ii]);
                    mma16816(acc[mf][(ip * 2 + ii) * 2 + 1], al[mf], bb[ii] + 2);
                }
        }
    }
}

__device__ __forceinline__ void epilogue(float acc[2][8][4], const float* bias,
                                         float* Xout, float* out, int out_off,
                                         int b0, int warp_m, int warp_n, int lane) {
    const int g = warp_n;
#pragma unroll
    for (int mf = 0; mf < 2; ++mf) {
        const int r0 = warp_m * 32 + mf * 16 + (lane >> 2);
        const int r1 = r0 + 8;
        const float bv0 = bias[r0], bv1 = bias[r1];
        float s0 = 0.f, s1 = 0.f;
#pragma unroll
        for (int nf = 0; nf < 8; ++nf) {
            float* c = acc[mf][nf];
            s0 += c[0] + c[1];
            s1 += c[2] + c[3];
            if (Xout) {
                const int d = nf * 8 + (lane & 3) * 2;
                float2 v0 = { c[0] + bv0, c[1] + bv0 };
                float2 v1 = { c[2] + bv1, c[3] + bv1 };
                *(float2*)(Xout + (size_t)(b0 + g) * ODIM * DDIM + r0 * DDIM + d) = v0;
                *(float2*)(Xout + (size_t)(b0 + g) * ODIM * DDIM + r1 * DDIM + d) = v1;
            }
        }
        s0 += __shfl_xor_sync(0xffffffffu, s0, 1);
        s0 += __shfl_xor_sync(0xffffffffu, s0, 2);
        s1 += __shfl_xor_sync(0xffffffffu, s1, 1);
        s1 += __shfl_xor_sync(0xffffffffu, s1, 2);
        if ((lane & 3) == 0) {
            out[(size_t)(b0 + g) * 384 + out_off + r0] = s0 + 64.f * bv0;
            out[(size_t)(b0 + g) * 384 + out_off + r1] = s1 + 64.f * bv1;
        }
    }
}

// ---------------- W pre-split (fp32 -> fp16 hi/lo, zero padded) ----------------
__global__ void split_w_kernel(const float* __restrict__ W, __half* __restrict__ hi,
                               __half* __restrict__ lo, int C, int Cpad) {
    int i = blockIdx.x * 256 + threadIdx.x;
    if (i >= ODIM * Cpad) return;
    int o = i / Cpad, cp = i - o * Cpad;
    float w = (cp < C) ? W[o * C + cp] : 0.f;
    __half h = __float2half_rn(w);
    hi[i] = h;
    lo[i] = __float2half_rn(w - __half2float(h));
}

// ---------------- Layer 1: Xi == X0, both operands from smem ----------------
__global__ __launch_bounds__(256, 2) void cin_l1(
    const float* __restrict__ X0,
    const __half* __restrict__ Whi, const __half* __restrict__ Wlo,
    const float* __restrict__ bias, float* __restrict__ Xout, float* __restrict__ out)
{
    extern __shared__ char smem[];
    constexpr int CPAD_ = 1536, C_ = 1521, NT = CPAD_ / KT;   // 48 tiles

    const int tid = threadIdx.x, wid = tid >> 5, lane = tid & 31;
    const int b0 = blockIdx.x * G;
    const int warp_m = wid >> 1, warp_n = wid & 1;
    const int lr = lane & 15, lc = lane >> 4;
    const int wrow = tid >> 1, whalf = tid & 1;
    const int n2 = (tid & 63) * 2, kh = tid >> 6;
    const int gg = n2 >> 6, dd = n2 & 63;

    float* x0s = (float*)smem;
    const float* x0_g = x0s + gg * FDIM * DDIM;
    const uint32_t stg = smem_u32(smem + OFF_STG);

    for (int i = tid; i < G * FDIM * DDIM; i += 256)
        x0s[i] = X0[(size_t)b0 * FDIM * DDIM + i];

    float acc[2][8][4];
#pragma unroll
    for (int a = 0; a < 2; ++a)
#pragma unroll
        for (int b = 0; b < 8; ++b)
#pragma unroll
            for (int c = 0; c < 4; ++c) acc[a][b][c] = 0.f;

    auto gen = [&](int t) {
        const uint32_t sb = stg + (t & 1) * STG_SZ;
        char* sbc = smem + OFF_STG + (t & 1) * STG_SZ;
        const int c0 = t * KT;
        stage_w<CPAD_>(sb, Whi, Wlo, c0, wrow, whalf);
#pragma unroll
        for (int j = 0; j < 8; ++j) {
            const int k = kh * 8 + j;
            const int c = c0 + k;
            float p0 = 0.f, p1 = 0.f;
            if (c < C_) {
                const int h = c / FDIM;
                const int m = c - h * FDIM;
                const float2 xv = *(const float2*)(x0_g + h * DDIM + dd);
                const float2 iv = *(const float2*)(x0_g + m * DDIM + dd);
                p0 = xv.x * iv.x; p1 = xv.y * iv.y;
            }
            __half2 hp = __floats2half2_rn(p0, p1);
            *(uint32_t*)(sbc + OFF_B + k * B_STRIDE + n2 * 2) = *(uint32_t*)&hp;
        }
    };

    __syncthreads();
    gen(0);
    CP_WAIT0();
    __syncthreads();

    for (int t = 0; t < NT; ++t) {
        if (t + 1 < NT) gen(t + 1);
        mma_tile(stg + (t & 1) * STG_SZ, warp_m, warp_n, lr, lc, acc);
        CP_WAIT0();
        __syncthreads();
    }
    epilogue(acc, bias, Xout, out, 0, b0, warp_m, warp_n, lane);
}

// ---------------- Layers 2/3: mb-outer loop, Xi m-block staged in smem ----------------
__global__ __launch_bounds__(256, 2) void cin_l23(
    const float* __restrict__ X0, const float* __restrict__ Xi,
    const __half* __restrict__ Whi, const __half* __restrict__ Wlo,
    const float* __restrict__ bias, float* __restrict__ Xout,
    float* __restrict__ out, int out_off)
{
    extern __shared__ char smem[];
    constexpr int CPAD_ = 4992, M_ = 128;

    const int tid = threadIdx.x, wid = tid >> 5, lane = tid & 31;
    const int b0 = blockIdx.x * G;
    const int warp_m = wid >> 1, warp_n = wid & 1;
    const int lr = lane & 15, lc = lane >> 4;
    const int wrow = tid >> 1, whalf = tid & 1;
    const int n2 = (tid & 63) * 2, kh = tid >> 6;
    const int gg = n2 >> 6, dd = n2 & 63;

    float* x0s = (float*)smem;
    float* xis = (float*)(smem + OFF_XIS);
    const float* x0_g = x0s + gg * FDIM * DDIM;
    const float* xi_g = xis + gg * KT * DDIM;
    const uint32_t stg = smem_u32(smem + OFF_STG);
    const uint32_t xis_u32 = smem_u32(xis);

    for (int i = tid; i < G * FDIM * DDIM; i += 256)
        x0s[i] = X0[(size_t)b0 * FDIM * DDIM + i];

    float acc[2][8][4];
#pragma unroll
    for (int a = 0; a < 2; ++a)
#pragma unroll
        for (int b = 0; b < 8; ++b)
#pragma unroll
            for (int c = 0; c < 4; ++c) acc[a][b][c] = 0.f;

    auto gen = [&](int mb, int h, int buf) {
        const uint32_t sb = stg + buf * STG_SZ;
        char* sbc = smem + OFF_STG + buf * STG_SZ;
        const int c0 = h * M_ + mb * KT;
        stage_w<CPAD_>(sb, Whi, Wlo, c0, wrow, whalf);
        const float2 xv = *(const float2*)(x0_g + h * DDIM + dd);
#pragma unroll
        for (int j = 0; j < 8; ++j) {
            const int k = kh * 8 + j;
            const float2 iv = *(const float2*)(xi_g + k * DDIM + dd);
            __half2 hp = __floats2half2_rn(xv.x * iv.x, xv.y * iv.y);
            *(uint32_t*)(sbc + OFF_B + k * B_STRIDE + n2 * 2) = *(uint32_t*)&hp;
        }
    };

    int t = 0;
    for (int mb = 0; mb < 4; ++mb) {
        __syncthreads();   // previous mb's gens done reading xis
        {
            const int i = tid;
#pragma unroll
            for (int it = 0; it < 4; ++it) {
                const int idx = it * 256 + i;
                const int g = idx >> 9, rem = idx & 511;
                const float* src = Xi + (size_t)(b0 + g) * M_ * DDIM + mb * KT * DDIM + rem * 4;
                CP_ASYNC16(xis_u32 + idx * 16, src);
            }
            CP_COMMIT();
            CP_WAIT0();
        }
        __syncthreads();
        gen(mb, 0, t & 1);
        CP_WAIT0();
        __syncthreads();
        for (int h = 0; h < FDIM; ++h, ++t) {
            if (h + 1 < FDIM) gen(mb, h + 1, (t + 1) & 1);
            mma_tile(stg + (t & 1) * STG_SZ, warp_m, warp_n, lr, lc, acc);
            CP_WAIT0();
            __syncthreads();
        }
    }
    epilogue(acc, bias, Xout, out, out_off, b0, warp_m, warp_n, lane);
}

// ---------------- launch ----------------
extern "C" void kernel_launch(void* const* d_in, const int* in_sizes, int n_in,
                              void* d_out, int out_size)
{
    const float* X0 = (const float*)d_in[0];
    const float* W1 = (const float*)d_in[1];
    const float* b1 = (const float*)d_in[2];
    const float* W2 = (const float*)d_in[3];
    const float* b2 = (const float*)d_in[4];
    const float* W3 = (const float*)d_in[5];
    const float* b3 = (const float*)d_in[6];
    float* out = (float*)d_out;

    float *X1p, *X2p;
    __half *W1h, *W1l, *W2h, *W2l, *W3h, *W3l;
    cudaGetSymbolAddress((void**)&X1p, g_X1);
    cudaGetSymbolAddress((void**)&X2p, g_X2);
    cudaGetSymbolAddress((void**)&W1h, g_W1hi);
    cudaGetSymbolAddress((void**)&W1l, g_W1lo);
    cudaGetSymbolAddress((void**)&W2h, g_W2hi);
    cudaGetSymbolAddress((void**)&W2l, g_W2lo);
    cudaGetSymbolAddress((void**)&W3h, g_W3hi);
    cudaGetSymbolAddress((void**)&W3l, g_W3lo);

    cudaFuncSetAttribute(cin_l1,  cudaFuncAttributeMaxDynamicSharedMemorySize, SMEM_TOT);
    cudaFuncSetAttribute(cin_l23, cudaFuncAttributeMaxDynamicSharedMemorySize, SMEM_TOT);

    split_w_kernel<<<(ODIM * 1536 + 255) / 256, 256>>>(W1, W1h, W1l, 1521, 1536);
    split_w_kernel<<<(ODIM * 4992 + 255) / 256, 256>>>(W2, W2h, W2l, 4992, 4992);
    split_w_kernel<<<(ODIM * 4992 + 255) / 256, 256>>>(W3, W3h, W3l, 4992, 4992);

    cin_l1 <<<BATCH / G, 256, SMEM_TOT>>>(X0, W1h, W1l, b1, X1p, out);
    cin_l23<<<BATCH / G, 256, SMEM_TOT>>>(X0, X1p, W2h, W2l, b2, X2p, out, 128);
    cin_l23<<<BATCH / G, 256, SMEM_TOT>>>(X0, X2p, W3h, W3l, b3, nullptr, out, 256);
}